// round 5
// baseline (speedup 1.0000x reference)
#include <cuda_runtime.h>
#include <cuda_fp16.h>
#include <cstdint>

// ============================================================================
// MQA_22436909154690 on GB300 (sm_103 base PTX target -> HMMA mma.sync path).
//
// Math: softmax over singleton axis == 1, so
//   out[b,l] = tile(v[b,l], H),  v = x @ Wv^T + bv,  Wv = Wkv[HD:2HD, :]
// => one GEMM [16384 x 2048] @ [2048 x 128] + bias + broadcast-x16 epilogue.
//
// R5 vs R4: KC 64 -> 128 (16 iterations instead of 32). R2-R4 all measured
// ~59us GEMM regardless of structure: per-iteration fixed overhead (barrier
// convoy + post-barrier memory burst + short mma runs) dominates. Halving the
// iteration count halves that fixed budget and doubles mma run length.
// ============================================================================

static constexpr int KDIM  = 2048;
static constexpr int MTILE = 64;
static constexpr int KC    = 128;           // K columns per chunk
static constexpr int NCH   = KDIM / KC;     // 16 chunks

// SMEM (bytes). Rows padded to 136 halves (272 B) -> ldmatrix row addresses
// land 68 words apart (68 mod 32 = 4): 8 rows hit 8 distinct bank groups.
static constexpr int AROW = 136;                      // halves per A/B row
static constexpr int SA0  = 0;                        // A buf0: [64][136] half
static constexpr int SA1  = 17408;                    // A buf1
static constexpr int SB0  = 34816;                    // B buf0: [128][136] half
static constexpr int SB1  = 34816 + 34816;            // B buf1
static constexpr int SMEM_TOTAL = SB1 + 34816;        // 104448
static constexpr int V_STRIDE = 132;                  // epilogue overlay

// Pre-converted Wv in fp16, chunk-major: [chunk16][n=128][k=128]
__device__ __align__(16) __half g_Wh[KDIM * 128];

// ---------------------------------------------------------------------------
__device__ __forceinline__ uint32_t smem_u32(const void* p) {
    uint32_t a;
    asm("{ .reg .u64 t; cvta.to.shared.u64 t, %1; cvt.u32.u64 %0, t; }" : "=r"(a) : "l"(p));
    return a;
}
__device__ __forceinline__ void ldsm4(uint32_t* r, uint32_t addr) {
    asm volatile("ldmatrix.sync.aligned.m8n8.x4.shared.b16 {%0,%1,%2,%3}, [%4];"
                 : "=r"(r[0]), "=r"(r[1]), "=r"(r[2]), "=r"(r[3]) : "r"(addr));
}
__device__ __forceinline__ void hmma(float* d, const uint32_t* a, uint32_t b0, uint32_t b1) {
    asm volatile("mma.sync.aligned.m16n8k16.row.col.f32.f16.f16.f32 "
                 "{%0,%1,%2,%3}, {%4,%5,%6,%7}, {%8,%9}, {%0,%1,%2,%3};"
                 : "+f"(d[0]), "+f"(d[1]), "+f"(d[2]), "+f"(d[3])
                 : "r"(a[0]), "r"(a[1]), "r"(a[2]), "r"(a[3]), "r"(b0), "r"(b1));
}
template <int N>
__device__ __forceinline__ void cpwait() {
    asm volatile("cp.async.wait_group %0;" :: "n"(N) : "memory");
}
__device__ __forceinline__ uint32_t h2u(__half2 h) { return *reinterpret_cast<uint32_t*>(&h); }

// ---------------------------------------------------------------------------
// Pre-kernel: Wv = Wkv rows 128..255 -> fp16, chunk-major [c][n][k128].
// ---------------------------------------------------------------------------
__global__ void convert_w_kernel(const float* __restrict__ Wkv) {
    int u = blockIdx.x * blockDim.x + threadIdx.x;    // 65536 units of 4 halves
    int c  = u >> 12;             // chunk (4096 units per chunk)
    int n  = (u >> 5) & 127;      // output column (32 units per row)
    int k4 = (u & 31) << 2;       // k within chunk
    float4 w = *(const float4*)(Wkv + (size_t)(128 + n) * KDIM + c * KC + k4);
    __half2 p0 = __float22half2_rn(make_float2(w.x, w.y));
    __half2 p1 = __float22half2_rn(make_float2(w.z, w.w));
    *(uint2*)(g_Wh + ((size_t)c * (128 * KC) + n * KC + k4)) = make_uint2(h2u(p0), h2u(p1));
}

// ---------------------------------------------------------------------------
// 256 CTAs x 256 threads, 2 CTAs/SM. 8 warps as 2(M) x 4(N): 32x32 frags.
// ---------------------------------------------------------------------------
__global__ void __launch_bounds__(256, 2)
mqa_gemm_kernel(const float* __restrict__ x, const float* __restrict__ bkv,
                float* __restrict__ out) {
    extern __shared__ char smem[];
    const uint32_t sb = smem_u32(smem);
    const int tid    = threadIdx.x;
    const int wid    = tid >> 5;
    const int lane   = tid & 31;
    const int warp_m = wid >> 2;
    const int warp_n = wid & 3;

    const float* xb = x + (size_t)blockIdx.x * MTILE * KDIM;

    // ldmatrix offsets within an A / B buffer
    uint32_t aOff[2];
    #pragma unroll
    for (int mf = 0; mf < 2; ++mf)
        aOff[mf] = (uint32_t)(warp_m * 32 + mf * 16 + (lane & 15)) * (AROW * 2)
                 + ((lane >> 4) << 4);
    uint32_t bOff[2];
    #pragma unroll
    for (int g = 0; g < 2; ++g)
        bOff[g] = (uint32_t)(warp_n * 32 + g * 16 + (lane & 15)) * (AROW * 2)
                 + ((lane >> 4) << 4);

    float acc[2][4][4];
    #pragma unroll
    for (int mf = 0; mf < 2; ++mf)
        #pragma unroll
        for (int nf = 0; nf < 4; ++nf)
            #pragma unroll
            for (int r = 0; r < 4; ++r) acc[mf][nf][r] = 0.f;

    // staged x chunk: 64 rows x 128 fp32 / 256 threads = 32 floats per thread
    float4 xs[4][2];

    auto ldx = [&](int ch) {
        #pragma unroll
        for (int i = 0; i < 4; ++i) {
            int u = tid + i * 256;                   // 8-float unit, 0..1023
            const float* p = xb + (size_t)(u >> 4) * KDIM + ch * KC + ((u & 15) << 3);
            xs[i][0] = ((const float4*)p)[0];
            xs[i][1] = ((const float4*)p)[1];
        }
    };
    auto stx = [&](int buf) {
        uint32_t base = (buf ? SA1 : SA0);
        #pragma unroll
        for (int i = 0; i < 4; ++i) {
            int u = tid + i * 256;
            __half2 h0 = __float22half2_rn(make_float2(xs[i][0].x, xs[i][0].y));
            __half2 h1 = __float22half2_rn(make_float2(xs[i][0].z, xs[i][0].w));
            __half2 h2 = __float22half2_rn(make_float2(xs[i][1].x, xs[i][1].y));
            __half2 h3 = __float22half2_rn(make_float2(xs[i][1].z, xs[i][1].w));
            uint4 v = make_uint4(h2u(h0), h2u(h1), h2u(h2), h2u(h3));
            *(uint4*)(smem + base + (u >> 4) * (AROW * 2) + ((u & 15) << 4)) = v;
        }
    };
    auto cpB = [&](int ch, int buf) {
        const __half* src = g_Wh + (size_t)ch * (128 * KC);
        uint32_t dbase = sb + (buf ? SB1 : SB0);
        #pragma unroll
        for (int j = 0; j < 8; ++j) {
            int idx = tid + j * 256;                 // 16B unit, 0..2047
            int n = idx >> 4, seg = idx & 15;
            uint32_t dst = dbase + n * (AROW * 2) + (seg << 4);
            const void* s = src + n * KC + seg * 8;
            asm volatile("cp.async.cg.shared.global [%0], [%1], 16;"
                         :: "r"(dst), "l"(s) : "memory");
        }
        asm volatile("cp.async.commit_group;" ::: "memory");
    };
    auto mmaChunk = [&](int buf) {
        uint32_t bA = sb + (buf ? SA1 : SA0);
        uint32_t bB = sb + (buf ? SB1 : SB0);
        #pragma unroll
        for (int kk = 0; kk < 8; ++kk) {             // 8 k16 steps
            uint32_t a[2][4];
            ldsm4(a[0], bA + aOff[0] + kk * 32);
            ldsm4(a[1], bA + aOff[1] + kk * 32);
            uint32_t b[2][4];
            ldsm4(b[0], bB + bOff[0] + kk * 32);
            ldsm4(b[1], bB + bOff[1] + kk * 32);
            #pragma unroll
            for (int mf = 0; mf < 2; ++mf) {
                hmma(acc[mf][0], a[mf], b[0][0], b[0][2]);
                hmma(acc[mf][1], a[mf], b[0][1], b[0][3]);
                hmma(acc[mf][2], a[mf], b[1][0], b[1][2]);
                hmma(acc[mf][3], a[mf], b[1][1], b[1][3]);
            }
        }
    };

    // --- prologue: B0 in flight, A0 stored, chunk 1 staged in regs ---
    cpB(0, 0);
    ldx(0);
    stx(0);                 // one-time exposed LDG latency
    ldx(1);
    cpwait<0>();            // B chunk 0 resident
    __syncthreads();

    // --- main loop: ONE barrier per 128-wide K chunk ---
    for (int it = 0; it < NCH; ++it) {
        // entering: A[it&1] + B[it&1] ready; xs holds chunk it+1 (in regs)
        if (it + 1 < NCH) {
            cpB(it + 1, (it + 1) & 1);   // B[it+1]: buffer freed at last barrier
            stx((it + 1) & 1);           // A[it+1] from regs
        }
        if (it + 2 < NCH) ldx(it + 2);   // LDGs get a full iteration to land
        mmaChunk(it & 1);
        cpwait<0>();                      // B[it+1] landed
        __syncthreads();                  // publishes A/B[it+1]
    }

    // --- epilogue ---
    float bias[4][2];
    {
        int c0 = warp_n * 32 + (lane & 3) * 2;
        #pragma unroll
        for (int nf = 0; nf < 4; ++nf) {
            bias[nf][0] = bkv[128 + c0 + nf * 8];
            bias[nf][1] = bkv[129 + c0 + nf * 8];
        }
    }
    __syncthreads();

    float* vsm = (float*)smem;
    {
        int r0 = warp_m * 32 + (lane >> 2);
        #pragma unroll
        for (int mf = 0; mf < 2; ++mf) {
            #pragma unroll
            for (int nf = 0; nf < 4; ++nf) {
                int r = r0 + mf * 16;
                int c = warp_n * 32 + nf * 8 + (lane & 3) * 2;
                vsm[r * V_STRIDE + c]           = acc[mf][nf][0] + bias[nf][0];
                vsm[r * V_STRIDE + c + 1]       = acc[mf][nf][1] + bias[nf][1];
                vsm[(r + 8) * V_STRIDE + c]     = acc[mf][nf][2] + bias[nf][0];
                vsm[(r + 8) * V_STRIDE + c + 1] = acc[mf][nf][3] + bias[nf][1];
            }
        }
    }
    __syncthreads();

    // Broadcast: each v row written 16x (one per head), fully coalesced.
    float* ob = out + (size_t)blockIdx.x * MTILE * 2048;
    for (int r = wid; r < MTILE; r += 8) {
        float4 val = *(const float4*)(vsm + r * V_STRIDE + lane * 4);
        float4* orow = (float4*)(ob + (size_t)r * 2048);
        #pragma unroll
        for (int h = 0; h < 16; ++h) orow[lane + h * 32] = val;
    }
}

// ---------------------------------------------------------------------------
extern "C" void kernel_launch(void* const* d_in, const int* in_sizes, int n_in,
                              void* d_out, int out_size) {
    const float* x   = (const float*)d_in[0];   // (4,4096,2048) fp32
    const float* Wkv = (const float*)d_in[3];   // (256,2048) fp32
    const float* bkv = (const float*)d_in[4];   // (256,) fp32
    float* out = (float*)d_out;                 // (4,4096,2048) fp32

    cudaFuncSetAttribute(mqa_gemm_kernel,
                         cudaFuncAttributeMaxDynamicSharedMemorySize, SMEM_TOTAL);

    convert_w_kernel<<<256, 256>>>(Wkv);
    mqa_gemm_kernel<<<16384 / MTILE, 256, SMEM_TOTAL>>>(x, bkv, out);
}

// round 6
// speedup vs baseline: 1.0747x; 1.0747x over previous
#include <cuda_runtime.h>
#include <cuda_fp16.h>
#include <cstdint>

// ============================================================================
// MQA_22436909154690 on GB300 (sm_103 base PTX target -> HMMA mma.sync path).
//
// Math: softmax over singleton axis == 1, so
//   out[b,l] = tile(v[b,l], H),  v = x @ Wv^T + bv,  Wv = Wkv[HD:2HD, :]
// => one GEMM [16384 x 2048] @ [2048 x 128] + bias + broadcast-x16 epilogue.
//
// R6 vs R4: x is no longer staged in registers (R5 showed reg pressure kills
// scheduling). x streams via cp.async into a 3-deep fp32 SMEM ring; the
// fp32->fp16 conversion is SMEM->SMEM. B double-buffered via cp.async.
// Odd CTAs start the K loop at chunk 16 (wrap) to decorrelate the two
// co-resident CTAs' bursts and barriers.
// ============================================================================

static constexpr int KDIM  = 2048;
static constexpr int MTILE = 64;
static constexpr int KC    = 64;            // K columns per chunk
static constexpr int NCH   = KDIM / KC;     // 32 chunks

// SMEM layout (bytes).
// A (fp16): rows padded to 72 halves (144 B) -> conflict-free ldmatrix/STS.
// X ring (fp32): rows padded to 68 floats (272 B) -> conflict-free LDS.128.
static constexpr int SA0 = 0;                         // A buf0: [64][72] half
static constexpr int SA1 = 9216;                      // A buf1
static constexpr int SX  = 18432;                     // X ring: 3 x [64][68] fp32
static constexpr int SXSZ = 64 * 272;                 // 17408
static constexpr int SB  = SX + 3 * SXSZ;             // 70656: B: 2 x [128][72] half
static constexpr int SBSZ = 18432;
static constexpr int SMEM_TOTAL = SB + 2 * SBSZ;      // 107520 (x2 CTAs = 210 KB/SM)
static constexpr int V_STRIDE = 132;                  // epilogue overlay

// Pre-converted Wv in fp16, chunk-major: [chunk32][n=128][k=64]
__device__ __align__(16) __half g_Wh[KDIM * 128];

// ---------------------------------------------------------------------------
__device__ __forceinline__ uint32_t smem_u32(const void* p) {
    uint32_t a;
    asm("{ .reg .u64 t; cvta.to.shared.u64 t, %1; cvt.u32.u64 %0, t; }" : "=r"(a) : "l"(p));
    return a;
}
__device__ __forceinline__ void ldsm4(uint32_t* r, uint32_t addr) {
    asm volatile("ldmatrix.sync.aligned.m8n8.x4.shared.b16 {%0,%1,%2,%3}, [%4];"
                 : "=r"(r[0]), "=r"(r[1]), "=r"(r[2]), "=r"(r[3]) : "r"(addr));
}
__device__ __forceinline__ void hmma(float* d, const uint32_t* a, uint32_t b0, uint32_t b1) {
    asm volatile("mma.sync.aligned.m16n8k16.row.col.f32.f16.f16.f32 "
                 "{%0,%1,%2,%3}, {%4,%5,%6,%7}, {%8,%9}, {%0,%1,%2,%3};"
                 : "+f"(d[0]), "+f"(d[1]), "+f"(d[2]), "+f"(d[3])
                 : "r"(a[0]), "r"(a[1]), "r"(a[2]), "r"(a[3]), "r"(b0), "r"(b1));
}
template <int N>
__device__ __forceinline__ void cpwait() {
    asm volatile("cp.async.wait_group %0;" :: "n"(N) : "memory");
}
__device__ __forceinline__ void cpcommit() {
    asm volatile("cp.async.commit_group;" ::: "memory");
}
__device__ __forceinline__ void cpa16(uint32_t dst, const void* src) {
    asm volatile("cp.async.cg.shared.global [%0], [%1], 16;" :: "r"(dst), "l"(src) : "memory");
}
__device__ __forceinline__ uint32_t h2u(__half2 h) { return *reinterpret_cast<uint32_t*>(&h); }

// ---------------------------------------------------------------------------
// Pre-kernel: Wv = Wkv rows 128..255 -> fp16, chunk-major [c][n][k64].
// ---------------------------------------------------------------------------
__global__ void convert_w_kernel(const float* __restrict__ Wkv) {
    int idx = blockIdx.x * blockDim.x + threadIdx.x;  // 65536 units of 4 halves
    int h4 = idx << 2;
    int c  = h4 >> 13;            // chunk
    int n  = (h4 >> 6) & 127;     // output column
    int k4 = h4 & 63;             // k within chunk
    float4 w = *(const float4*)(Wkv + (size_t)(128 + n) * KDIM + c * KC + k4);
    __half2 p0 = __float22half2_rn(make_float2(w.x, w.y));
    __half2 p1 = __float22half2_rn(make_float2(w.z, w.w));
    *(uint2*)(g_Wh + h4) = make_uint2(h2u(p0), h2u(p1));
}

// ---------------------------------------------------------------------------
// 256 CTAs x 256 threads, 2 CTAs/SM. 8 warps as 2(M) x 4(N): 32x32 frags.
// ---------------------------------------------------------------------------
__global__ void __launch_bounds__(256, 2)
mqa_gemm_kernel(const float* __restrict__ x, const float* __restrict__ bkv,
                float* __restrict__ out) {
    extern __shared__ char smem[];
    const uint32_t sb = smem_u32(smem);
    const int tid    = threadIdx.x;
    const int wid    = tid >> 5;
    const int lane   = tid & 31;
    const int warp_m = wid >> 2;
    const int warp_n = wid & 3;
    const int skew   = (blockIdx.x & 1) * (NCH / 2);   // phase-offset odd CTAs

    const float* xb = x + (size_t)blockIdx.x * MTILE * KDIM;

    // ldmatrix offsets within an A / B buffer (row stride 144 B)
    uint32_t aOff[2];
    #pragma unroll
    for (int mf = 0; mf < 2; ++mf)
        aOff[mf] = (uint32_t)(warp_m * 32 + mf * 16 + (lane & 15)) * 144 + ((lane >> 4) << 4);
    uint32_t bOff[2];
    #pragma unroll
    for (int g = 0; g < 2; ++g)
        bOff[g] = (uint32_t)(warp_n * 32 + g * 16 + (lane & 15)) * 144 + ((lane >> 4) << 4);

    float acc[2][4][4];
    #pragma unroll
    for (int mf = 0; mf < 2; ++mf)
        #pragma unroll
        for (int nf = 0; nf < 4; ++nf)
            #pragma unroll
            for (int r = 0; r < 4; ++r) acc[mf][nf][r] = 0.f;

    // cp.async x chunk (16 KB fp32) into ring slot. 4 x 16B per thread.
    auto cpx = [&](int ch, int slot) {
        uint32_t dbase = sb + SX + slot * SXSZ;
        #pragma unroll
        for (int j = 0; j < 4; ++j) {
            int u = tid + j * 256;              // 16B unit: row = u>>4, col16 = u&15
            uint32_t dst = dbase + (u >> 4) * 272 + ((u & 15) << 4);
            const void* s = xb + (size_t)(u >> 4) * KDIM + ch * KC + ((u & 15) << 2);
            cpa16(dst, s);
        }
    };
    // cp.async B chunk (16 KB fp16). 4 x 16B per thread.
    auto cpB = [&](int ch, int buf) {
        const __half* src = g_Wh + (size_t)ch * (128 * KC);
        uint32_t dbase = sb + SB + buf * SBSZ;
        #pragma unroll
        for (int j = 0; j < 4; ++j) {
            int u = tid + j * 256;              // n = u>>3, seg = u&7
            uint32_t dst = dbase + (u >> 3) * 144 + ((u & 7) << 4);
            const void* s = src + (u >> 3) * KC + ((u & 7) << 3);
            cpa16(dst, s);
        }
    };
    // SMEM->SMEM conversion: ring slot (fp32) -> A buffer (fp16).
    // Thread t: row = t&63, 16 consecutive floats at col (t>>6)*16.
    auto convert = [&](int slot, int abuf) {
        const char* src = smem + SX + slot * SXSZ + (tid & 63) * 272 + ((tid >> 6) << 6);
        char*       dst = smem + (abuf ? SA1 : SA0) + (tid & 63) * 144 + ((tid >> 6) << 5);
        float4 f0 = ((const float4*)src)[0];
        float4 f1 = ((const float4*)src)[1];
        float4 f2 = ((const float4*)src)[2];
        float4 f3 = ((const float4*)src)[3];
        uint4 o0 = make_uint4(h2u(__float22half2_rn(make_float2(f0.x, f0.y))),
                              h2u(__float22half2_rn(make_float2(f0.z, f0.w))),
                              h2u(__float22half2_rn(make_float2(f1.x, f1.y))),
                              h2u(__float22half2_rn(make_float2(f1.z, f1.w))));
        uint4 o1 = make_uint4(h2u(__float22half2_rn(make_float2(f2.x, f2.y))),
                              h2u(__float22half2_rn(make_float2(f2.z, f2.w))),
                              h2u(__float22half2_rn(make_float2(f3.x, f3.y))),
                              h2u(__float22half2_rn(make_float2(f3.z, f3.w))));
        ((uint4*)dst)[0] = o0;
        ((uint4*)dst)[1] = o1;
    };
    auto mmaChunk = [&](int buf) {
        uint32_t bA = sb + (buf ? SA1 : SA0);
        uint32_t bB = sb + SB + buf * SBSZ;
        #pragma unroll
        for (int kk = 0; kk < 4; ++kk) {
            uint32_t a[2][4];
            ldsm4(a[0], bA + aOff[0] + kk * 32);
            ldsm4(a[1], bA + aOff[1] + kk * 32);
            uint32_t b[2][4];
            ldsm4(b[0], bB + bOff[0] + kk * 32);
            ldsm4(b[1], bB + bOff[1] + kk * 32);
            #pragma unroll
            for (int mf = 0; mf < 2; ++mf) {
                hmma(acc[mf][0], a[mf], b[0][0], b[0][2]);
                hmma(acc[mf][1], a[mf], b[0][1], b[0][3]);
                hmma(acc[mf][2], a[mf], b[1][0], b[1][2]);
                hmma(acc[mf][3], a[mf], b[1][1], b[1][3]);
            }
        }
    };

    // --- prologue: B0 + x0 + x1 in flight, then convert x0 -> A[0] ---
    cpB((0 + skew) & 31, 0); cpcommit();
    cpx((0 + skew) & 31, 0); cpcommit();
    cpx((1 + skew) & 31, 1); cpcommit();
    cpwait<0>();
    __syncthreads();
    convert(0, 0);
    __syncthreads();

    // --- main loop: ONE barrier per chunk ---
    for (int it = 0; it < NCH; ++it) {
        // entering: A[it&1] converted, B[it&1] loaded, x slot (it+1)%3 landed
        if (it + 1 < NCH) { cpB((it + 1 + skew) & 31, (it + 1) & 1); cpcommit(); }
        if (it + 2 < NCH) { cpx((it + 2 + skew) & 31, (it + 2) % 3); cpcommit(); }
        if (it + 1 < NCH) convert((it + 1) % 3, (it + 1) & 1);
        mmaChunk(it & 1);
        cpwait<0>();
        __syncthreads();
    }

    // --- epilogue ---
    float bias[4][2];
    {
        int c0 = warp_n * 32 + (lane & 3) * 2;
        #pragma unroll
        for (int nf = 0; nf < 4; ++nf) {
            bias[nf][0] = bkv[128 + c0 + nf * 8];
            bias[nf][1] = bkv[129 + c0 + nf * 8];
        }
    }
    __syncthreads();

    float* vsm = (float*)smem;
    {
        int r0 = warp_m * 32 + (lane >> 2);
        #pragma unroll
        for (int mf = 0; mf < 2; ++mf) {
            #pragma unroll
            for (int nf = 0; nf < 4; ++nf) {
                int r = r0 + mf * 16;
                int c = warp_n * 32 + nf * 8 + (lane & 3) * 2;
                vsm[r * V_STRIDE + c]           = acc[mf][nf][0] + bias[nf][0];
                vsm[r * V_STRIDE + c + 1]       = acc[mf][nf][1] + bias[nf][1];
                vsm[(r + 8) * V_STRIDE + c]     = acc[mf][nf][2] + bias[nf][0];
                vsm[(r + 8) * V_STRIDE + c + 1] = acc[mf][nf][3] + bias[nf][1];
            }
        }
    }
    __syncthreads();

    // Broadcast: each v row written 16x (one per head), fully coalesced.
    float* ob = out + (size_t)blockIdx.x * MTILE * 2048;
    for (int r = wid; r < MTILE; r += 8) {
        float4 val = *(const float4*)(vsm + r * V_STRIDE + lane * 4);
        float4* orow = (float4*)(ob + (size_t)r * 2048);
        #pragma unroll
        for (int h = 0; h < 16; ++h) orow[lane + h * 32] = val;
    }
}

// ---------------------------------------------------------------------------
extern "C" void kernel_launch(void* const* d_in, const int* in_sizes, int n_in,
                              void* d_out, int out_size) {
    const float* x   = (const float*)d_in[0];   // (4,4096,2048) fp32
    const float* Wkv = (const float*)d_in[3];   // (256,2048) fp32
    const float* bkv = (const float*)d_in[4];   // (256,) fp32
    float* out = (float*)d_out;                 // (4,4096,2048) fp32

    cudaFuncSetAttribute(mqa_gemm_kernel,
                         cudaFuncAttributeMaxDynamicSharedMemorySize, SMEM_TOTAL);

    convert_w_kernel<<<256, 256>>>(Wkv);
    mqa_gemm_kernel<<<16384 / MTILE, 256, SMEM_TOTAL>>>(x, bkv, out);
}

// round 7
// speedup vs baseline: 1.1967x; 1.1135x over previous
#include <cuda_runtime.h>
#include <cuda_fp16.h>
#include <cstdint>

// ============================================================================
// MQA_22436909154690 on GB300 (sm_103 base PTX target -> HMMA mma.sync path).
//
// Math: softmax over singleton axis == 1, so
//   out[b,l] = tile(v[b,l], H),  v = x @ Wv^T + bv,  Wv = Wkv[HD:2HD, :]
// => one GEMM [16384 x 2048] @ [2048 x 128] + bias + broadcast-x16 epilogue.
//
// R7: warp-specialized producer/consumer with mbarrier ring (sm_90-level PTX,
// legal at base sm_103 target). R2-R6 all pinned at ~60us GEMM: monolithic
// loop couples memory issue to compute barriers (DRAM 44%, L1 48%, tensor 23%,
// nothing saturated). Producers (4 warps) stream x (LDG->cvt->STS) and B
// (cp.async) into a 4-deep ring; consumers (8 warps) do ldsm+hmma only, no
// __syncthreads in the loop.
// ============================================================================

static constexpr int KDIM  = 2048;
static constexpr int MTILE = 64;
static constexpr int KC    = 64;
static constexpr int NCH   = KDIM / KC;       // 32 stages
static constexpr int NSLOT = 4;               // ring depth

// Stage = A [64][72]half (9216 B) + B [128][72]half (18432 B)
static constexpr int SB_OFF = 9216;
static constexpr int STAGE  = 27648;
static constexpr int BARS   = NSLOT * STAGE;  // 110592: full/empty pairs, 16 B each
static constexpr int SMEM_TOTAL = BARS + 128; // 110720 (x2 CTAs = 221 KB/SM)
static constexpr int V_STRIDE = 132;          // epilogue overlay in slot 0/1 area

// Pre-converted Wv fp16, chunk-major: [chunk32][n=128][k=64]
__device__ __align__(16) __half g_Wh[KDIM * 128];

// ---------------------------------------------------------------------------
__device__ __forceinline__ uint32_t smem_u32(const void* p) {
    uint32_t a;
    asm("{ .reg .u64 t; cvta.to.shared.u64 t, %1; cvt.u32.u64 %0, t; }" : "=r"(a) : "l"(p));
    return a;
}
__device__ __forceinline__ void ldsm4(uint32_t* r, uint32_t addr) {
    asm volatile("ldmatrix.sync.aligned.m8n8.x4.shared.b16 {%0,%1,%2,%3}, [%4];"
                 : "=r"(r[0]), "=r"(r[1]), "=r"(r[2]), "=r"(r[3]) : "r"(addr));
}
__device__ __forceinline__ void hmma(float* d, const uint32_t* a, uint32_t b0, uint32_t b1) {
    asm volatile("mma.sync.aligned.m16n8k16.row.col.f32.f16.f16.f32 "
                 "{%0,%1,%2,%3}, {%4,%5,%6,%7}, {%8,%9}, {%0,%1,%2,%3};"
                 : "+f"(d[0]), "+f"(d[1]), "+f"(d[2]), "+f"(d[3])
                 : "r"(a[0]), "r"(a[1]), "r"(a[2]), "r"(a[3]), "r"(b0), "r"(b1));
}
__device__ __forceinline__ void cpa16(uint32_t dst, const void* src) {
    asm volatile("cp.async.cg.shared.global [%0], [%1], 16;" :: "r"(dst), "l"(src) : "memory");
}
__device__ __forceinline__ void mbar_init(uint32_t bar, uint32_t cnt) {
    asm volatile("mbarrier.init.shared.b64 [%0], %1;" :: "r"(bar), "r"(cnt) : "memory");
}
__device__ __forceinline__ void mbar_arrive(uint32_t bar) {
    asm volatile("mbarrier.arrive.shared.b64 _, [%0];" :: "r"(bar) : "memory");
}
__device__ __forceinline__ void mbar_arrive_cpasync(uint32_t bar) {
    asm volatile("cp.async.mbarrier.arrive.noinc.shared.b64 [%0];" :: "r"(bar) : "memory");
}
__device__ __forceinline__ void mbar_wait(uint32_t bar, uint32_t parity) {
    asm volatile(
        "{\n\t.reg .pred P;\n\t"
        "W%=:\n\t"
        "mbarrier.try_wait.parity.shared.b64 P, [%0], %1, 0x989680;\n\t"
        "@!P bra W%=;\n\t}"
        :: "r"(bar), "r"(parity) : "memory");
}
__device__ __forceinline__ uint32_t h2u(__half2 h) { return *reinterpret_cast<uint32_t*>(&h); }

// ---------------------------------------------------------------------------
// Pre-kernel: Wv = Wkv rows 128..255 -> fp16, chunk-major [c][n][k64].
// ---------------------------------------------------------------------------
__global__ void convert_w_kernel(const float* __restrict__ Wkv) {
    int idx = blockIdx.x * blockDim.x + threadIdx.x;  // 65536 units of 4 halves
    int h4 = idx << 2;
    int c  = h4 >> 13;
    int n  = (h4 >> 6) & 127;
    int k4 = h4 & 63;
    float4 w = *(const float4*)(Wkv + (size_t)(128 + n) * KDIM + c * KC + k4);
    __half2 p0 = __float22half2_rn(make_float2(w.x, w.y));
    __half2 p1 = __float22half2_rn(make_float2(w.z, w.w));
    *(uint2*)(g_Wh + h4) = make_uint2(h2u(p0), h2u(p1));
}

// ---------------------------------------------------------------------------
// 256 CTAs x 384 threads (8 consumer + 4 producer warps), 2 CTAs/SM.
// ---------------------------------------------------------------------------
__global__ void __launch_bounds__(384, 2)
mqa_gemm_kernel(const float* __restrict__ x, const float* __restrict__ bkv,
                float* __restrict__ out) {
    extern __shared__ char smem[];
    const uint32_t sb = smem_u32(smem);
    const int tid  = threadIdx.x;
    const int wid  = tid >> 5;
    const int lane = tid & 31;

    const float* xb = x + (size_t)blockIdx.x * MTILE * KDIM;

    if (tid == 0) {
        #pragma unroll
        for (int i = 0; i < NSLOT; ++i) {
            mbar_init(sb + BARS + i * 16,     256);  // full: 128 STS arrives + 128 cp.async arrives
            mbar_init(sb + BARS + i * 16 + 8, 256);  // empty: 256 consumer arrives
        }
    }
    __syncthreads();

    // Consumer state lives at function scope so the epilogue (after the final
    // top-level barrier) can use it. Producer/consumer reg sets are disjoint
    // in liveness, so ptxas overlaps them.
    float acc[2][4][4];
    const int warp_m = wid >> 2;      // valid for wid 0..7
    const int warp_n = wid & 3;

    if (tid >= 256) {
        // ================= PRODUCER: 4 warps =================
        const int pt = tid - 256;     // 0..127
        float4 xs[8];                 // 32 floats: one x stage slice

        auto ldx = [&](int ch) {
            #pragma unroll
            for (int j = 0; j < 8; ++j) {
                int u = pt + j * 128;                  // float4 unit, 0..1023
                xs[j] = *(const float4*)(xb + (size_t)(u >> 4) * KDIM
                                         + ch * KC + ((u & 15) << 2));
            }
        };

        ldx(0);
        for (int s = 0; s < NCH; ++s) {
            const int slot = s & 3;
            const uint32_t full  = sb + BARS + slot * 16;
            const uint32_t empty = full + 8;
            // first ring pass: empty bar phase-bit 0, wait parity 1 passes immediately
            mbar_wait(empty, ((s >> 2) & 1) ^ 1);

            // B: 16 KB cp.async into stage slot, completion -> full (async arrive)
            const __half* bsrc = g_Wh + (size_t)s * (128 * KC);
            const uint32_t bbase = sb + slot * STAGE + SB_OFF;
            #pragma unroll
            for (int j = 0; j < 8; ++j) {
                int u = pt + j * 128;                  // 16B unit: n = u>>3, seg = u&7
                cpa16(bbase + (u >> 3) * 144 + ((u & 7) << 4),
                      bsrc + (u >> 3) * KC + ((u & 7) << 3));
            }
            mbar_arrive_cpasync(full);

            // A: cvt staged x chunk -> fp16 -> STS
            const uint32_t abase = sb + slot * STAGE;
            #pragma unroll
            for (int j = 0; j < 8; ++j) {
                int u = pt + j * 128;
                uint32_t lo = h2u(__float22half2_rn(make_float2(xs[j].x, xs[j].y)));
                uint32_t hi = h2u(__float22half2_rn(make_float2(xs[j].z, xs[j].w)));
                asm volatile("st.shared.v2.u32 [%0], {%1,%2};"
                             :: "r"(abase + (u >> 4) * 144 + ((u & 15) << 3)),
                                "r"(lo), "r"(hi) : "memory");
            }
            if (s + 1 < NCH) ldx(s + 1);               // a full stage to land
            mbar_arrive(full);                         // release: STS visible after wait
        }
    } else {
        // ================= CONSUMER: 8 warps =================
        uint32_t aRel[2], bRel[2];
        #pragma unroll
        for (int mf = 0; mf < 2; ++mf)
            aRel[mf] = (uint32_t)(warp_m * 32 + mf * 16 + (lane & 15)) * 144
                     + ((lane >> 4) << 4);
        #pragma unroll
        for (int g = 0; g < 2; ++g)
            bRel[g] = SB_OFF + (uint32_t)(warp_n * 32 + g * 16 + (lane & 15)) * 144
                    + ((lane >> 4) << 4);

        #pragma unroll
        for (int mf = 0; mf < 2; ++mf)
            #pragma unroll
            for (int nf = 0; nf < 4; ++nf)
                #pragma unroll
                for (int r = 0; r < 4; ++r) acc[mf][nf][r] = 0.f;

        for (int s = 0; s < NCH; ++s) {
            const int slot = s & 3;
            const uint32_t full  = sb + BARS + slot * 16;
            const uint32_t empty = full + 8;
            mbar_wait(full, (s >> 2) & 1);

            const uint32_t stg = sb + slot * STAGE;
            #pragma unroll
            for (int kk = 0; kk < 4; ++kk) {
                uint32_t a[2][4];
                ldsm4(a[0], stg + aRel[0] + kk * 32);
                ldsm4(a[1], stg + aRel[1] + kk * 32);
                uint32_t b[2][4];
                ldsm4(b[0], stg + bRel[0] + kk * 32);
                ldsm4(b[1], stg + bRel[1] + kk * 32);
                #pragma unroll
                for (int mf = 0; mf < 2; ++mf) {
                    hmma(acc[mf][0], a[mf], b[0][0], b[0][2]);
                    hmma(acc[mf][1], a[mf], b[0][1], b[0][3]);
                    hmma(acc[mf][2], a[mf], b[1][0], b[1][2]);
                    hmma(acc[mf][3], a[mf], b[1][1], b[1][3]);
                }
            }
            mbar_arrive(empty);
        }
    }

    __syncthreads();   // all stages consumed; slot memory free for overlay

    // --- epilogue: consumers add bias and stage v tile in SMEM ---
    float* vsm = (float*)smem;
    if (tid < 256) {
        float bias[4][2];
        {
            int c0 = warp_n * 32 + (lane & 3) * 2;
            #pragma unroll
            for (int nf = 0; nf < 4; ++nf) {
                bias[nf][0] = bkv[128 + c0 + nf * 8];
                bias[nf][1] = bkv[129 + c0 + nf * 8];
            }
        }
        int r0 = warp_m * 32 + (lane >> 2);
        #pragma unroll
        for (int mf = 0; mf < 2; ++mf) {
            #pragma unroll
            for (int nf = 0; nf < 4; ++nf) {
                int r = r0 + mf * 16;
                int c = warp_n * 32 + nf * 8 + (lane & 3) * 2;
                vsm[r * V_STRIDE + c]           = acc[mf][nf][0] + bias[nf][0];
                vsm[r * V_STRIDE + c + 1]       = acc[mf][nf][1] + bias[nf][1];
                vsm[(r + 8) * V_STRIDE + c]     = acc[mf][nf][2] + bias[nf][0];
                vsm[(r + 8) * V_STRIDE + c + 1] = acc[mf][nf][3] + bias[nf][1];
            }
        }
    }
    __syncthreads();

    // Broadcast: all 12 warps; each v row written 16x (one per head), coalesced.
    float* ob = out + (size_t)blockIdx.x * MTILE * 2048;
    for (int r = wid; r < MTILE; r += 12) {
        float4 val = *(const float4*)(vsm + r * V_STRIDE + lane * 4);
        float4* orow = (float4*)(ob + (size_t)r * 2048);
        #pragma unroll
        for (int h = 0; h < 16; ++h) orow[lane + h * 32] = val;
    }
}

// ---------------------------------------------------------------------------
extern "C" void kernel_launch(void* const* d_in, const int* in_sizes, int n_in,
                              void* d_out, int out_size) {
    const float* x   = (const float*)d_in[0];   // (4,4096,2048) fp32
    const float* Wkv = (const float*)d_in[3];   // (256,2048) fp32
    const float* bkv = (const float*)d_in[4];   // (256,) fp32
    float* out = (float*)d_out;                 // (4,4096,2048) fp32

    cudaFuncSetAttribute(mqa_gemm_kernel,
                         cudaFuncAttributeMaxDynamicSharedMemorySize, SMEM_TOTAL);

    convert_w_kernel<<<256, 256>>>(Wkv);
    mqa_gemm_kernel<<<16384 / MTILE, 384, SMEM_TOTAL>>>(x, bkv, out);
}